// round 14
// baseline (speedup 1.0000x reference)
#include <cuda_runtime.h>
#include <math.h>

#define TPAD 65
// sx[64][65] + sh[64][65] + qc[4096] + kc[4096] + vc[4096]
#define SMEM_FLOATS (2 * 64 * TPAD + 3 * 4096)
#define SMEM_BYTES  (SMEM_FLOATS * 4)

// ---- packed f32x2 helpers (SASS FFMA2 is only reachable via PTX) ----
__device__ __forceinline__ unsigned long long pack2(float lo, float hi) {
    unsigned long long r;
    asm("mov.b64 %0, {%1, %2};" : "=l"(r) : "f"(lo), "f"(hi));
    return r;
}
__device__ __forceinline__ unsigned long long bcast2(float v) {
    unsigned long long r;
    asm("mov.b64 %0, {%1, %1};" : "=l"(r) : "f"(v));
    return r;
}
__device__ __forceinline__ void fma2(unsigned long long& d,
                                     unsigned long long a, unsigned long long b) {
    asm("fma.rn.f32x2 %0, %1, %2, %0;" : "+l"(d) : "l"(a), "l"(b));
}
__device__ __forceinline__ unsigned long long mul2(unsigned long long a,
                                                   unsigned long long b) {
    unsigned long long r;
    asm("mul.rn.f32x2 %0, %1, %2;" : "=l"(r) : "l"(a), "l"(b));
    return r;
}
__device__ __forceinline__ float2 unpack2(unsigned long long v) {
    float lo, hi;
    asm("mov.b64 {%0, %1}, %2;" : "=f"(lo), "=f"(hi) : "l"(v));
    return make_float2(lo, hi);
}
__device__ __forceinline__ float hadd2(unsigned long long v) {
    float2 t = unpack2(v);
    return t.x + t.y;
}

__global__ __launch_bounds__(256, 2)
void block_kernel(
    const float* __restrict__ x,
    const float* __restrict__ ln1_w, const float* __restrict__ ln1_b,
    const float* __restrict__ wq, const float* __restrict__ wk, const float* __restrict__ wv,
    const float* __restrict__ proj_w, const float* __restrict__ proj_b,
    const float* __restrict__ ln2_w, const float* __restrict__ ln2_b,
    const float* __restrict__ fc1_w, const float* __restrict__ fc1_b,
    const float* __restrict__ fc2_w, const float* __restrict__ fc2_b,
    float* __restrict__ out)
{
    extern __shared__ float smem[];
    float* sx = smem;                 // [64][TPAD] residual stream
    float* sh = sx + 64 * TPAD;       // [64][TPAD] LN out / attn out / LN2 out
    float* qc = sh + 64 * TPAD;       // [8][64][8] compact q ; later FF [64][64]
    float* kc = qc + 4096;            // [8][64][8]
    float* vc = kc + 4096;            // [8][64][8]

    const int b   = blockIdx.x;
    const int tid = threadIdx.x;
    const float* xb = x + (size_t)b * 4096;

    // ---------------- load x ----------------
    for (int i = tid; i < 1024; i += 256) {
        float4 v = ((const float4*)xb)[i];
        int r = i >> 4, c = (i & 15) * 4;
        float* d = &sx[r * TPAD + c];
        d[0] = v.x; d[1] = v.y; d[2] = v.z; d[3] = v.w;
    }
    __syncthreads();

    const int lr = tid >> 2;      // LN: 64 rows x 4 threads
    const int lq = tid & 3;

    // ---------------- LN1 ----------------
    {
        const float* row = &sx[lr * TPAD + lq * 16];
        float s1 = 0.f, s2 = 0.f;
        #pragma unroll
        for (int i = 0; i < 16; i++) { float v = row[i]; s1 += v; s2 += v * v; }
        s1 += __shfl_xor_sync(0xffffffffu, s1, 1);
        s2 += __shfl_xor_sync(0xffffffffu, s2, 1);
        s1 += __shfl_xor_sync(0xffffffffu, s1, 2);
        s2 += __shfl_xor_sync(0xffffffffu, s2, 2);
        float mu = s1 * 0.015625f;
        float rs = rsqrtf(s2 * 0.015625f - mu * mu + 1e-5f);
        float* hrow = &sh[lr * TPAD + lq * 16];
        #pragma unroll
        for (int i = 0; i < 16; i++) {
            int c = lq * 16 + i;
            hrow[i] = (row[i] - mu) * rs * ln1_w[c] + ln1_b[c];
        }
    }
    __syncthreads();

    const int col4 = (tid & 15) * 4;   // matmul tile: 4 cols
    const int row4 = (tid >> 4) * 4;   // 4 rows

    // ---------------- q, k, v projections (packed f32x2) ----------------
    // wq layout [H=8, C=64, hs=8]; output col j = h*8+d -> weight idx h*512 + c*8 + d
    // compact staging: qc[h*512 + t*8 + d]
    {
        unsigned long long aq[4][2], ak[4][2], av[4][2];
        #pragma unroll
        for (int i = 0; i < 4; i++)
            #pragma unroll
            for (int j = 0; j < 2; j++) { aq[i][j] = 0ull; ak[i][j] = 0ull; av[i][j] = 0ull; }
        const int woff = (col4 >> 3) * 512 + (col4 & 7);
        const ulonglong2* wqp = (const ulonglong2*)(wq + woff);
        const ulonglong2* wkp = (const ulonglong2*)(wk + woff);
        const ulonglong2* wvp = (const ulonglong2*)(wv + woff);
        #pragma unroll 2
        for (int c = 0; c < 64; c++) {
            ulonglong2 bq = wqp[c * 2];
            ulonglong2 bk = wkp[c * 2];
            ulonglong2 bv = wvp[c * 2];
            #pragma unroll
            for (int i = 0; i < 4; i++) {
                unsigned long long aa = bcast2(sh[(row4 + i) * TPAD + c]);
                fma2(aq[i][0], aa, bq.x); fma2(aq[i][1], aa, bq.y);
                fma2(ak[i][0], aa, bk.x); fma2(ak[i][1], aa, bk.y);
                fma2(av[i][0], aa, bv.x); fma2(av[i][1], aa, bv.y);
            }
        }
        const int cbase = (col4 >> 3) * 512 + (col4 & 7);   // h*512 + d0
        #pragma unroll
        for (int i = 0; i < 4; i++) {
            float2 q0 = unpack2(aq[i][0]), q1 = unpack2(aq[i][1]);
            float2 k0 = unpack2(ak[i][0]), k1 = unpack2(ak[i][1]);
            float2 v0 = unpack2(av[i][0]), v1 = unpack2(av[i][1]);
            const int o = cbase + (row4 + i) * 8;            // 16B-aligned (d0 in {0,4})
            *(float4*)&qc[o] = make_float4(q0.x, q0.y, q1.x, q1.y);
            *(float4*)&kc[o] = make_float4(k0.x, k0.y, k1.x, k1.y);
            *(float4*)&vc[o] = make_float4(v0.x, v0.y, v1.x, v1.y);
        }
    }
    __syncthreads();

    // ---------------- attention: streaming softmax, packed f32x2, zero shfl ----------------
    // warp w = head w; lane owns rows t1=lane and t2=lane+32.
    // Scores are O(0.05): exp without max-subtraction is safe; normalize at end (exact).
    {
        const int wid  = tid >> 5;
        const int lane = tid & 31;
        const int hb   = wid * 8;            // for sh output addressing
        const ulonglong2* qh2 = (const ulonglong2*)&qc[wid * 512];
        const ulonglong2* kh2 = (const ulonglong2*)&kc[wid * 512];
        const ulonglong2* vh2 = (const ulonglong2*)&vc[wid * 512];
        const int t1 = lane, t2 = lane + 32;

        // q rows, pre-scaled by 0.125 (packed)
        unsigned long long q1p[4], q2p[4];
        {
            const unsigned long long sc = bcast2(0.125f);
            ulonglong2 a = qh2[t1 * 2], bqq = qh2[t1 * 2 + 1];
            q1p[0] = mul2(a.x, sc); q1p[1] = mul2(a.y, sc);
            q1p[2] = mul2(bqq.x, sc); q1p[3] = mul2(bqq.y, sc);
            ulonglong2 c = qh2[t2 * 2], dqq = qh2[t2 * 2 + 1];
            q2p[0] = mul2(c.x, sc); q2p[1] = mul2(c.y, sc);
            q2p[2] = mul2(dqq.x, sc); q2p[3] = mul2(dqq.y, sc);
        }
        unsigned long long acc1[4], accB[4];
        #pragma unroll
        for (int j = 0; j < 4; j++) { acc1[j] = 0ull; accB[j] = 0ull; }
        float S1 = 0.f, S2 = 0.f;

        // s in [0,32): row2 always unmasked (t2 >= 32 > s); row1 masked by s<=t1
        #pragma unroll 4
        for (int s = 0; s < 32; s++) {
            ulonglong2 ka = kh2[s * 2], kb = kh2[s * 2 + 1];   // warp-uniform -> broadcast
            ulonglong2 va = vh2[s * 2], vb = vh2[s * 2 + 1];
            unsigned long long d1p = mul2(q1p[0], ka.x);
            fma2(d1p, q1p[1], ka.y); fma2(d1p, q1p[2], kb.x); fma2(d1p, q1p[3], kb.y);
            unsigned long long d2p = mul2(q2p[0], ka.x);
            fma2(d2p, q2p[1], ka.y); fma2(d2p, q2p[2], kb.x); fma2(d2p, q2p[3], kb.y);
            float e1 = (s <= t1) ? __expf(hadd2(d1p)) : 0.f;
            float e2 = __expf(hadd2(d2p));
            S1 += e1; S2 += e2;
            unsigned long long e1p = bcast2(e1), e2p = bcast2(e2);
            fma2(acc1[0], e1p, va.x); fma2(acc1[1], e1p, va.y);
            fma2(acc1[2], e1p, vb.x); fma2(acc1[3], e1p, vb.y);
            fma2(accB[0], e2p, va.x); fma2(accB[1], e2p, va.y);
            fma2(accB[2], e2p, vb.x); fma2(accB[3], e2p, vb.y);
        }
        // s in [32,64): only row2 can attend; masked by s<=t2
        #pragma unroll 4
        for (int s = 32; s < 64; s++) {
            ulonglong2 ka = kh2[s * 2], kb = kh2[s * 2 + 1];
            ulonglong2 va = vh2[s * 2], vb = vh2[s * 2 + 1];
            unsigned long long d2p = mul2(q2p[0], ka.x);
            fma2(d2p, q2p[1], ka.y); fma2(d2p, q2p[2], kb.x); fma2(d2p, q2p[3], kb.y);
            float e2 = (s <= t2) ? __expf(hadd2(d2p)) : 0.f;
            S2 += e2;
            unsigned long long e2p = bcast2(e2);
            fma2(accB[0], e2p, va.x); fma2(accB[1], e2p, va.y);
            fma2(accB[2], e2p, vb.x); fma2(accB[3], e2p, vb.y);
        }
        const float i1 = 1.0f / S1, i2 = 1.0f / S2;
        #pragma unroll
        for (int j = 0; j < 4; j++) {
            float2 a = unpack2(acc1[j]);
            sh[t1 * TPAD + hb + j * 2]     = a.x * i1;
            sh[t1 * TPAD + hb + j * 2 + 1] = a.y * i1;
            float2 bb = unpack2(accB[j]);
            sh[t2 * TPAD + hb + j * 2]     = bb.x * i2;
            sh[t2 * TPAD + hb + j * 2 + 1] = bb.y * i2;
        }
    }
    __syncthreads();

    // ---------------- proj + residual into sx (packed) ----------------
    {
        unsigned long long ap[4][2];
        float4 pb = *(const float4*)(proj_b + col4);
        #pragma unroll
        for (int i = 0; i < 4; i++) {
            ap[i][0] = pack2(pb.x, pb.y);
            ap[i][1] = pack2(pb.z, pb.w);
        }
        const ulonglong2* wp = (const ulonglong2*)(proj_w + col4);
        #pragma unroll 4
        for (int c = 0; c < 64; c++) {
            ulonglong2 bw = wp[c * 16];
            #pragma unroll
            for (int i = 0; i < 4; i++) {
                unsigned long long aa = bcast2(sh[(row4 + i) * TPAD + c]);
                fma2(ap[i][0], aa, bw.x);
                fma2(ap[i][1], aa, bw.y);
            }
        }
        #pragma unroll
        for (int i = 0; i < 4; i++) {
            float2 p0 = unpack2(ap[i][0]), p1 = unpack2(ap[i][1]);
            float* d = &sx[(row4 + i) * TPAD + col4];
            d[0] += p0.x; d[1] += p0.y; d[2] += p1.x; d[3] += p1.y;
        }
    }
    __syncthreads();

    // ---------------- LN2 -> sh ----------------
    {
        const float* row = &sx[lr * TPAD + lq * 16];
        float s1 = 0.f, s2 = 0.f;
        #pragma unroll
        for (int i = 0; i < 16; i++) { float v = row[i]; s1 += v; s2 += v * v; }
        s1 += __shfl_xor_sync(0xffffffffu, s1, 1);
        s2 += __shfl_xor_sync(0xffffffffu, s2, 1);
        s1 += __shfl_xor_sync(0xffffffffu, s1, 2);
        s2 += __shfl_xor_sync(0xffffffffu, s2, 2);
        float mu = s1 * 0.015625f;
        float rs = rsqrtf(s2 * 0.015625f - mu * mu + 1e-5f);
        float* hrow = &sh[lr * TPAD + lq * 16];
        #pragma unroll
        for (int i = 0; i < 16; i++) {
            int c = lq * 16 + i;
            hrow[i] = (row[i] - mu) * rs * ln2_w[c] + ln2_b[c];
        }
    }
    __syncthreads();

    // ---------------- feed-forward in 4 chunks of 64 cols (packed) ----------------
    unsigned long long acc2[4][2];
    {
        float4 b2 = *(const float4*)(fc2_b + col4);
        #pragma unroll
        for (int i = 0; i < 4; i++) {
            acc2[i][0] = pack2(b2.x, b2.y);
            acc2[i][1] = pack2(b2.z, b2.w);
        }
    }
    float* sff = qc;   // reuse compact q buffer as [64][64]
    for (int ch = 0; ch < 4; ch++) {
        unsigned long long af[4][2];
        float4 b1 = *(const float4*)(fc1_b + ch * 64 + col4);
        #pragma unroll
        for (int i = 0; i < 4; i++) {
            af[i][0] = pack2(b1.x, b1.y);
            af[i][1] = pack2(b1.z, b1.w);
        }
        const ulonglong2* w1 = (const ulonglong2*)(fc1_w + ch * 64 + col4);
        #pragma unroll 4
        for (int c = 0; c < 64; c++) {
            ulonglong2 bw = w1[c * 64];   // +c*256 floats
            #pragma unroll
            for (int i = 0; i < 4; i++) {
                unsigned long long aa = bcast2(sh[(row4 + i) * TPAD + c]);
                fma2(af[i][0], aa, bw.x);
                fma2(af[i][1], aa, bw.y);
            }
        }
        __syncthreads();   // previous chunk's sff fully consumed
        #pragma unroll
        for (int i = 0; i < 4; i++) {
            float2 f0 = unpack2(af[i][0]), f1 = unpack2(af[i][1]);
            *(float4*)&sff[(row4 + i) * 64 + col4] =
                make_float4(fmaxf(f0.x, 0.f), fmaxf(f0.y, 0.f),
                            fmaxf(f1.x, 0.f), fmaxf(f1.y, 0.f));
        }
        __syncthreads();
        const ulonglong2* w2 = (const ulonglong2*)(fc2_w + ch * 4096 + col4);
        #pragma unroll 4
        for (int c = 0; c < 64; c++) {
            ulonglong2 bw = w2[c * 16];   // +c*64 floats
            #pragma unroll
            for (int i = 0; i < 4; i++) {
                unsigned long long aa = bcast2(sff[(row4 + i) * 64 + c]);
                fma2(acc2[i][0], aa, bw.x);
                fma2(acc2[i][1], aa, bw.y);
            }
        }
    }

    // ---------------- final residual + store ----------------
    {
        float* ob = out + (size_t)b * 4096;
        #pragma unroll
        for (int i = 0; i < 4; i++) {
            float2 a0 = unpack2(acc2[i][0]), a1 = unpack2(acc2[i][1]);
            const float* sxr = &sx[(row4 + i) * TPAD + col4];
            float4 o;
            o.x = sxr[0] + a0.x;
            o.y = sxr[1] + a0.y;
            o.z = sxr[2] + a1.x;
            o.w = sxr[3] + a1.y;
            *(float4*)(ob + (row4 + i) * 64 + col4) = o;
        }
    }
}

extern "C" void kernel_launch(void* const* d_in, const int* in_sizes, int n_in,
                              void* d_out, int out_size)
{
    cudaFuncSetAttribute(block_kernel, cudaFuncAttributeMaxDynamicSharedMemorySize, SMEM_BYTES);
    int B = in_sizes[0] / 4096;   // B*T*C / (64*64)
    block_kernel<<<B, 256, SMEM_BYTES>>>(
        (const float*)d_in[0],
        (const float*)d_in[1],  (const float*)d_in[2],
        (const float*)d_in[3],  (const float*)d_in[4],  (const float*)d_in[5],
        (const float*)d_in[6],  (const float*)d_in[7],
        (const float*)d_in[8],  (const float*)d_in[9],
        (const float*)d_in[10], (const float*)d_in[11],
        (const float*)d_in[12], (const float*)d_in[13],
        (float*)d_out);
}

// round 16
// speedup vs baseline: 1.1724x; 1.1724x over previous
#include <cuda_runtime.h>
#include <math.h>

#define XPAD 65
#define SHP  68
// sx[64][65] + sh[64][68] + qc[4096] + kc[4096] + vc[4096]
#define SMEM_FLOATS (64 * XPAD + 64 * SHP + 3 * 4096)
#define SMEM_BYTES  (SMEM_FLOATS * 4)

// ---- packed f32x2 helpers (SASS FFMA2 is only reachable via PTX) ----
__device__ __forceinline__ unsigned long long pack2(float lo, float hi) {
    unsigned long long r;
    asm("mov.b64 %0, {%1, %2};" : "=l"(r) : "f"(lo), "f"(hi));
    return r;
}
__device__ __forceinline__ unsigned long long bcast2(float v) {
    unsigned long long r;
    asm("mov.b64 %0, {%1, %1};" : "=l"(r) : "f"(v));
    return r;
}
__device__ __forceinline__ void fma2(unsigned long long& d,
                                     unsigned long long a, unsigned long long b) {
    asm("fma.rn.f32x2 %0, %1, %2, %0;" : "+l"(d) : "l"(a), "l"(b));
}
__device__ __forceinline__ unsigned long long mul2(unsigned long long a,
                                                   unsigned long long b) {
    unsigned long long r;
    asm("mul.rn.f32x2 %0, %1, %2;" : "=l"(r) : "l"(a), "l"(b));
    return r;
}
__device__ __forceinline__ float2 unpack2(unsigned long long v) {
    float lo, hi;
    asm("mov.b64 {%0, %1}, %2;" : "=f"(lo), "=f"(hi) : "l"(v));
    return make_float2(lo, hi);
}
__device__ __forceinline__ float hadd2(unsigned long long v) {
    float2 t = unpack2(v);
    return t.x + t.y;
}

__global__ __launch_bounds__(256, 2)
void block_kernel(
    const float* __restrict__ x,
    const float* __restrict__ ln1_w, const float* __restrict__ ln1_b,
    const float* __restrict__ wq, const float* __restrict__ wk, const float* __restrict__ wv,
    const float* __restrict__ proj_w, const float* __restrict__ proj_b,
    const float* __restrict__ ln2_w, const float* __restrict__ ln2_b,
    const float* __restrict__ fc1_w, const float* __restrict__ fc1_b,
    const float* __restrict__ fc2_w, const float* __restrict__ fc2_b,
    float* __restrict__ out)
{
    extern __shared__ float smem[];
    float* sx = smem;                 // [64][XPAD] residual stream (scalar access)
    float* sh = sx + 64 * XPAD;       // [64][SHP] LN out / attn out / LN2 out (vector access)
    float* qc = sh + 64 * SHP;        // [8][64][8] compact q ; later FF [64][64]
    float* kc = qc + 4096;            // [8][64][8]
    float* vc = kc + 4096;            // [8][64][8]

    const int b   = blockIdx.x;
    const int tid = threadIdx.x;
    const float* xb = x + (size_t)b * 4096;

    // ---------------- load x ----------------
    for (int i = tid; i < 1024; i += 256) {
        float4 v = ((const float4*)xb)[i];
        int r = i >> 4, c = (i & 15) * 4;
        float* d = &sx[r * XPAD + c];
        d[0] = v.x; d[1] = v.y; d[2] = v.z; d[3] = v.w;
    }
    __syncthreads();

    const int lr = tid >> 2;      // LN: 64 rows x 4 threads
    const int lq = tid & 3;

    // ---------------- LN1 (vectorized writes) ----------------
    {
        const float* row = &sx[lr * XPAD + lq * 16];
        float s1 = 0.f, s2 = 0.f;
        #pragma unroll
        for (int i = 0; i < 16; i++) { float v = row[i]; s1 += v; s2 += v * v; }
        s1 += __shfl_xor_sync(0xffffffffu, s1, 1);
        s2 += __shfl_xor_sync(0xffffffffu, s2, 1);
        s1 += __shfl_xor_sync(0xffffffffu, s1, 2);
        s2 += __shfl_xor_sync(0xffffffffu, s2, 2);
        float mu = s1 * 0.015625f;
        float rs = rsqrtf(s2 * 0.015625f - mu * mu + 1e-5f);
        float4* hv = (float4*)&sh[lr * SHP + lq * 16];
        #pragma unroll
        for (int j = 0; j < 4; j++) {
            int c = lq * 16 + j * 4;
            float4 o;
            o.x = (row[j*4+0] - mu) * rs * ln1_w[c+0] + ln1_b[c+0];
            o.y = (row[j*4+1] - mu) * rs * ln1_w[c+1] + ln1_b[c+1];
            o.z = (row[j*4+2] - mu) * rs * ln1_w[c+2] + ln1_b[c+2];
            o.w = (row[j*4+3] - mu) * rs * ln1_w[c+3] + ln1_b[c+3];
            hv[j] = o;
        }
    }
    __syncthreads();

    const int col4 = (tid & 15) * 4;   // matmul tile: 4 cols
    const int row4 = (tid >> 4) * 4;   // 4 rows

    // ---------------- q, k, v projections (packed f32x2, k-vectorized LDS) ----------------
    // wq layout [H=8, C=64, hs=8]; output col j = h*8+d -> weight idx h*512 + c*8 + d
    // compact staging: qc[h*512 + t*8 + d]
    {
        unsigned long long aq[4][2], ak[4][2], av[4][2];
        #pragma unroll
        for (int i = 0; i < 4; i++)
            #pragma unroll
            for (int j = 0; j < 2; j++) { aq[i][j] = 0ull; ak[i][j] = 0ull; av[i][j] = 0ull; }
        const int woff = (col4 >> 3) * 512 + (col4 & 7);
        const ulonglong2* wqp = (const ulonglong2*)(wq + woff);
        const ulonglong2* wkp = (const ulonglong2*)(wk + woff);
        const ulonglong2* wvp = (const ulonglong2*)(wv + woff);
        for (int cb = 0; cb < 64; cb += 4) {
            float a4[4][4];
            #pragma unroll
            for (int i = 0; i < 4; i++)
                *(float4*)a4[i] = *(const float4*)&sh[(row4 + i) * SHP + cb];
            #pragma unroll
            for (int kk = 0; kk < 4; kk++) {
                ulonglong2 bq = wqp[(cb + kk) * 2];
                ulonglong2 bk = wkp[(cb + kk) * 2];
                ulonglong2 bv = wvp[(cb + kk) * 2];
                #pragma unroll
                for (int i = 0; i < 4; i++) {
                    unsigned long long aa = bcast2(a4[i][kk]);
                    fma2(aq[i][0], aa, bq.x); fma2(aq[i][1], aa, bq.y);
                    fma2(ak[i][0], aa, bk.x); fma2(ak[i][1], aa, bk.y);
                    fma2(av[i][0], aa, bv.x); fma2(av[i][1], aa, bv.y);
                }
            }
        }
        const int cbase = (col4 >> 3) * 512 + (col4 & 7);   // h*512 + d0
        #pragma unroll
        for (int i = 0; i < 4; i++) {
            float2 q0 = unpack2(aq[i][0]), q1 = unpack2(aq[i][1]);
            float2 k0 = unpack2(ak[i][0]), k1 = unpack2(ak[i][1]);
            float2 v0 = unpack2(av[i][0]), v1 = unpack2(av[i][1]);
            const int o = cbase + (row4 + i) * 8;            // 16B-aligned (d0 in {0,4})
            *(float4*)&qc[o] = make_float4(q0.x, q0.y, q1.x, q1.y);
            *(float4*)&kc[o] = make_float4(k0.x, k0.y, k1.x, k1.y);
            *(float4*)&vc[o] = make_float4(v0.x, v0.y, v1.x, v1.y);
        }
    }
    __syncthreads();

    // ---------------- attention: streaming softmax, packed f32x2, zero shfl ----------------
    // warp w = head w; lane owns rows t1=lane and t2=lane+32.
    // Scores are O(0.05): exp without max-subtraction is safe; normalize at end (exact).
    {
        const int wid  = tid >> 5;
        const int lane = tid & 31;
        const int hb   = wid * 8;            // for sh output addressing
        const ulonglong2* qh2 = (const ulonglong2*)&qc[wid * 512];
        const ulonglong2* kh2 = (const ulonglong2*)&kc[wid * 512];
        const ulonglong2* vh2 = (const ulonglong2*)&vc[wid * 512];
        const int t1 = lane, t2 = lane + 32;

        // q rows, pre-scaled by 0.125 (packed)
        unsigned long long q1p[4], q2p[4];
        {
            const unsigned long long sc = bcast2(0.125f);
            ulonglong2 a = qh2[t1 * 2], bqq = qh2[t1 * 2 + 1];
            q1p[0] = mul2(a.x, sc); q1p[1] = mul2(a.y, sc);
            q1p[2] = mul2(bqq.x, sc); q1p[3] = mul2(bqq.y, sc);
            ulonglong2 c = qh2[t2 * 2], dqq = qh2[t2 * 2 + 1];
            q2p[0] = mul2(c.x, sc); q2p[1] = mul2(c.y, sc);
            q2p[2] = mul2(dqq.x, sc); q2p[3] = mul2(dqq.y, sc);
        }
        unsigned long long acc1[4], accB[4];
        #pragma unroll
        for (int j = 0; j < 4; j++) { acc1[j] = 0ull; accB[j] = 0ull; }
        float S1 = 0.f, S2 = 0.f;

        // s in [0,32): row2 always unmasked (t2 >= 32 > s); row1 masked by s<=t1
        #pragma unroll 4
        for (int s = 0; s < 32; s++) {
            ulonglong2 ka = kh2[s * 2], kb = kh2[s * 2 + 1];   // warp-uniform -> broadcast
            ulonglong2 va = vh2[s * 2], vb = vh2[s * 2 + 1];
            unsigned long long d1p = mul2(q1p[0], ka.x);
            fma2(d1p, q1p[1], ka.y); fma2(d1p, q1p[2], kb.x); fma2(d1p, q1p[3], kb.y);
            unsigned long long d2p = mul2(q2p[0], ka.x);
            fma2(d2p, q2p[1], ka.y); fma2(d2p, q2p[2], kb.x); fma2(d2p, q2p[3], kb.y);
            float e1 = (s <= t1) ? __expf(hadd2(d1p)) : 0.f;
            float e2 = __expf(hadd2(d2p));
            S1 += e1; S2 += e2;
            unsigned long long e1p = bcast2(e1), e2p = bcast2(e2);
            fma2(acc1[0], e1p, va.x); fma2(acc1[1], e1p, va.y);
            fma2(acc1[2], e1p, vb.x); fma2(acc1[3], e1p, vb.y);
            fma2(accB[0], e2p, va.x); fma2(accB[1], e2p, va.y);
            fma2(accB[2], e2p, vb.x); fma2(accB[3], e2p, vb.y);
        }
        // s in [32,64): only row2 can attend; masked by s<=t2
        #pragma unroll 4
        for (int s = 32; s < 64; s++) {
            ulonglong2 ka = kh2[s * 2], kb = kh2[s * 2 + 1];
            ulonglong2 va = vh2[s * 2], vb = vh2[s * 2 + 1];
            unsigned long long d2p = mul2(q2p[0], ka.x);
            fma2(d2p, q2p[1], ka.y); fma2(d2p, q2p[2], kb.x); fma2(d2p, q2p[3], kb.y);
            float e2 = (s <= t2) ? __expf(hadd2(d2p)) : 0.f;
            S2 += e2;
            unsigned long long e2p = bcast2(e2);
            fma2(accB[0], e2p, va.x); fma2(accB[1], e2p, va.y);
            fma2(accB[2], e2p, vb.x); fma2(accB[3], e2p, vb.y);
        }
        const float i1 = 1.0f / S1, i2 = 1.0f / S2;
        {
            float2 a0 = unpack2(acc1[0]), a1 = unpack2(acc1[1]);
            float2 a2 = unpack2(acc1[2]), a3 = unpack2(acc1[3]);
            float4* o1 = (float4*)&sh[t1 * SHP + hb];
            o1[0] = make_float4(a0.x * i1, a0.y * i1, a1.x * i1, a1.y * i1);
            o1[1] = make_float4(a2.x * i1, a2.y * i1, a3.x * i1, a3.y * i1);
            float2 b0 = unpack2(accB[0]), b1 = unpack2(accB[1]);
            float2 b2 = unpack2(accB[2]), b3 = unpack2(accB[3]);
            float4* o2 = (float4*)&sh[t2 * SHP + hb];
            o2[0] = make_float4(b0.x * i2, b0.y * i2, b1.x * i2, b1.y * i2);
            o2[1] = make_float4(b2.x * i2, b2.y * i2, b3.x * i2, b3.y * i2);
        }
    }
    __syncthreads();

    // ---------------- proj + residual into sx (packed, k-vectorized) ----------------
    {
        unsigned long long ap[4][2];
        float4 pb = *(const float4*)(proj_b + col4);
        #pragma unroll
        for (int i = 0; i < 4; i++) {
            ap[i][0] = pack2(pb.x, pb.y);
            ap[i][1] = pack2(pb.z, pb.w);
        }
        const ulonglong2* wp = (const ulonglong2*)(proj_w + col4);
        for (int cb = 0; cb < 64; cb += 4) {
            float a4[4][4];
            #pragma unroll
            for (int i = 0; i < 4; i++)
                *(float4*)a4[i] = *(const float4*)&sh[(row4 + i) * SHP + cb];
            #pragma unroll
            for (int kk = 0; kk < 4; kk++) {
                ulonglong2 bw = wp[(cb + kk) * 16];
                #pragma unroll
                for (int i = 0; i < 4; i++) {
                    unsigned long long aa = bcast2(a4[i][kk]);
                    fma2(ap[i][0], aa, bw.x);
                    fma2(ap[i][1], aa, bw.y);
                }
            }
        }
        #pragma unroll
        for (int i = 0; i < 4; i++) {
            float2 p0 = unpack2(ap[i][0]), p1 = unpack2(ap[i][1]);
            float* d = &sx[(row4 + i) * XPAD + col4];
            d[0] += p0.x; d[1] += p0.y; d[2] += p1.x; d[3] += p1.y;
        }
    }
    __syncthreads();

    // ---------------- LN2 -> sh (vectorized writes) ----------------
    {
        const float* row = &sx[lr * XPAD + lq * 16];
        float s1 = 0.f, s2 = 0.f;
        #pragma unroll
        for (int i = 0; i < 16; i++) { float v = row[i]; s1 += v; s2 += v * v; }
        s1 += __shfl_xor_sync(0xffffffffu, s1, 1);
        s2 += __shfl_xor_sync(0xffffffffu, s2, 1);
        s1 += __shfl_xor_sync(0xffffffffu, s1, 2);
        s2 += __shfl_xor_sync(0xffffffffu, s2, 2);
        float mu = s1 * 0.015625f;
        float rs = rsqrtf(s2 * 0.015625f - mu * mu + 1e-5f);
        float4* hv = (float4*)&sh[lr * SHP + lq * 16];
        #pragma unroll
        for (int j = 0; j < 4; j++) {
            int c = lq * 16 + j * 4;
            float4 o;
            o.x = (row[j*4+0] - mu) * rs * ln2_w[c+0] + ln2_b[c+0];
            o.y = (row[j*4+1] - mu) * rs * ln2_w[c+1] + ln2_b[c+1];
            o.z = (row[j*4+2] - mu) * rs * ln2_w[c+2] + ln2_b[c+2];
            o.w = (row[j*4+3] - mu) * rs * ln2_w[c+3] + ln2_b[c+3];
            hv[j] = o;
        }
    }
    __syncthreads();

    // ---------------- feed-forward in 4 chunks of 64 cols (packed, k-vectorized) ----------------
    unsigned long long acc2[4][2];
    {
        float4 b2 = *(const float4*)(fc2_b + col4);
        #pragma unroll
        for (int i = 0; i < 4; i++) {
            acc2[i][0] = pack2(b2.x, b2.y);
            acc2[i][1] = pack2(b2.z, b2.w);
        }
    }
    float* sff = qc;   // reuse compact q buffer as [64][64]
    for (int ch = 0; ch < 4; ch++) {
        unsigned long long af[4][2];
        float4 b1 = *(const float4*)(fc1_b + ch * 64 + col4);
        #pragma unroll
        for (int i = 0; i < 4; i++) {
            af[i][0] = pack2(b1.x, b1.y);
            af[i][1] = pack2(b1.z, b1.w);
        }
        const ulonglong2* w1 = (const ulonglong2*)(fc1_w + ch * 64 + col4);
        for (int cb = 0; cb < 64; cb += 4) {
            float a4[4][4];
            #pragma unroll
            for (int i = 0; i < 4; i++)
                *(float4*)a4[i] = *(const float4*)&sh[(row4 + i) * SHP + cb];
            #pragma unroll
            for (int kk = 0; kk < 4; kk++) {
                ulonglong2 bw = w1[(cb + kk) * 64];   // +c*256 floats
                #pragma unroll
                for (int i = 0; i < 4; i++) {
                    unsigned long long aa = bcast2(a4[i][kk]);
                    fma2(af[i][0], aa, bw.x);
                    fma2(af[i][1], aa, bw.y);
                }
            }
        }
        __syncthreads();   // previous chunk's sff fully consumed
        #pragma unroll
        for (int i = 0; i < 4; i++) {
            float2 f0 = unpack2(af[i][0]), f1 = unpack2(af[i][1]);
            *(float4*)&sff[(row4 + i) * 64 + col4] =
                make_float4(fmaxf(f0.x, 0.f), fmaxf(f0.y, 0.f),
                            fmaxf(f1.x, 0.f), fmaxf(f1.y, 0.f));
        }
        __syncthreads();
        const ulonglong2* w2 = (const ulonglong2*)(fc2_w + ch * 4096 + col4);
        for (int cb = 0; cb < 64; cb += 4) {
            float a4[4][4];
            #pragma unroll
            for (int i = 0; i < 4; i++)
                *(float4*)a4[i] = *(const float4*)&sff[(row4 + i) * 64 + cb];
            #pragma unroll
            for (int kk = 0; kk < 4; kk++) {
                ulonglong2 bw = w2[(cb + kk) * 16];   // +c*64 floats
                #pragma unroll
                for (int i = 0; i < 4; i++) {
                    unsigned long long aa = bcast2(a4[i][kk]);
                    fma2(acc2[i][0], aa, bw.x);
                    fma2(acc2[i][1], aa, bw.y);
                }
            }
        }
    }

    // ---------------- final residual + store ----------------
    {
        float* ob = out + (size_t)b * 4096;
        #pragma unroll
        for (int i = 0; i < 4; i++) {
            float2 a0 = unpack2(acc2[i][0]), a1 = unpack2(acc2[i][1]);
            const float* sxr = &sx[(row4 + i) * XPAD + col4];
            float4 o;
            o.x = sxr[0] + a0.x;
            o.y = sxr[1] + a0.y;
            o.z = sxr[2] + a1.x;
            o.w = sxr[3] + a1.y;
            *(float4*)(ob + (row4 + i) * 64 + col4) = o;
        }
    }
}

extern "C" void kernel_launch(void* const* d_in, const int* in_sizes, int n_in,
                              void* d_out, int out_size)
{
    cudaFuncSetAttribute(block_kernel, cudaFuncAttributeMaxDynamicSharedMemorySize, SMEM_BYTES);
    int B = in_sizes[0] / 4096;   // B*T*C / (64*64)
    block_kernel<<<B, 256, SMEM_BYTES>>>(
        (const float*)d_in[0],
        (const float*)d_in[1],  (const float*)d_in[2],
        (const float*)d_in[3],  (const float*)d_in[4],  (const float*)d_in[5],
        (const float*)d_in[6],  (const float*)d_in[7],
        (const float*)d_in[8],  (const float*)d_in[9],
        (const float*)d_in[10], (const float*)d_in[11],
        (const float*)d_in[12], (const float*)d_in[13],
        (float*)d_out);
}

// round 17
// speedup vs baseline: 1.4771x; 1.2598x over previous
#include <cuda_runtime.h>
#include <math.h>

#define XPAD 65
#define SHP  68
// sx[4160] + sh[4352] + scratch[13056] (weights staged, then qkv/FF)
#define SMEM_FLOATS (64 * XPAD + 64 * SHP + 3 * 4352)
#define SMEM_BYTES  (SMEM_FLOATS * 4)

// ---- packed f32x2 helpers (SASS FFMA2 is only reachable via PTX) ----
__device__ __forceinline__ unsigned long long pack2(float lo, float hi) {
    unsigned long long r;
    asm("mov.b64 %0, {%1, %2};" : "=l"(r) : "f"(lo), "f"(hi));
    return r;
}
__device__ __forceinline__ unsigned long long bcast2(float v) {
    unsigned long long r;
    asm("mov.b64 %0, {%1, %1};" : "=l"(r) : "f"(v));
    return r;
}
__device__ __forceinline__ void fma2(unsigned long long& d,
                                     unsigned long long a, unsigned long long b) {
    asm("fma.rn.f32x2 %0, %1, %2, %0;" : "+l"(d) : "l"(a), "l"(b));
}
__device__ __forceinline__ unsigned long long mul2(unsigned long long a,
                                                   unsigned long long b) {
    unsigned long long r;
    asm("mul.rn.f32x2 %0, %1, %2;" : "=l"(r) : "l"(a), "l"(b));
    return r;
}
__device__ __forceinline__ float2 unpack2(unsigned long long v) {
    float lo, hi;
    asm("mov.b64 {%0, %1}, %2;" : "=f"(lo), "=f"(hi) : "l"(v));
    return make_float2(lo, hi);
}
__device__ __forceinline__ float hadd2(unsigned long long v) {
    float2 t = unpack2(v);
    return t.x + t.y;
}

__global__ __launch_bounds__(256, 2)
void block_kernel(
    const float* __restrict__ x,
    const float* __restrict__ ln1_w, const float* __restrict__ ln1_b,
    const float* __restrict__ wq, const float* __restrict__ wk, const float* __restrict__ wv,
    const float* __restrict__ proj_w, const float* __restrict__ proj_b,
    const float* __restrict__ ln2_w, const float* __restrict__ ln2_b,
    const float* __restrict__ fc1_w, const float* __restrict__ fc1_b,
    const float* __restrict__ fc2_w, const float* __restrict__ fc2_b,
    float* __restrict__ out)
{
    extern __shared__ float smem[];
    float* sx = smem;                   // [64][XPAD] residual stream
    float* sh = sx + 64 * XPAD;         // [64][SHP] LN out / attn out / LN2 out
    float* scratch = sh + 64 * SHP;     // 13056 floats, two lifetimes:
    float* wqs = scratch;               //   phase 1: wq transposed [64][68]
    float* wks = scratch + 4352;        //            wk transposed
    float* wvs = scratch + 8704;        //            wv transposed
    float* qc = scratch;                //   phase 2: [8][64][8] compact q ; later FF [64][64]
    float* kc = scratch + 4096;
    float* vc = scratch + 8192;

    const int b   = blockIdx.x;
    const int tid = threadIdx.x;
    const float* xb = x + (size_t)b * 4096;

    // ---------------- load x + stage qkv weights transposed ----------------
    // gmem [h][c][d] (h*512 + c*8 + d) -> smem [c][j] (c*68 + h*8 + d), j = h*8+d
    for (int i = tid; i < 1024; i += 256) {
        float4 v = ((const float4*)xb)[i];
        int r = i >> 4, c = (i & 15) * 4;
        float* d = &sx[r * XPAD + c];
        d[0] = v.x; d[1] = v.y; d[2] = v.z; d[3] = v.w;
    }
    #pragma unroll
    for (int t = 0; t < 4; t++) {
        int i = tid + t * 256;
        int h = i >> 7, c = (i >> 1) & 63, d0 = (i & 1) * 4;
        int o = c * 68 + h * 8 + d0;
        *(float4*)&wqs[o] = ((const float4*)wq)[i];
        *(float4*)&wks[o] = ((const float4*)wk)[i];
        *(float4*)&wvs[o] = ((const float4*)wv)[i];
    }
    __syncthreads();

    const int lr = tid >> 2;      // LN: 64 rows x 4 threads
    const int lq = tid & 3;

    // ---------------- LN1 (vectorized writes) ----------------
    {
        const float* row = &sx[lr * XPAD + lq * 16];
        float s1 = 0.f, s2 = 0.f;
        #pragma unroll
        for (int i = 0; i < 16; i++) { float v = row[i]; s1 += v; s2 += v * v; }
        s1 += __shfl_xor_sync(0xffffffffu, s1, 1);
        s2 += __shfl_xor_sync(0xffffffffu, s2, 1);
        s1 += __shfl_xor_sync(0xffffffffu, s1, 2);
        s2 += __shfl_xor_sync(0xffffffffu, s2, 2);
        float mu = s1 * 0.015625f;
        float rs = rsqrtf(s2 * 0.015625f - mu * mu + 1e-5f);
        float4* hv = (float4*)&sh[lr * SHP + lq * 16];
        #pragma unroll
        for (int j = 0; j < 4; j++) {
            int c = lq * 16 + j * 4;
            float4 o;
            o.x = (row[j*4+0] - mu) * rs * ln1_w[c+0] + ln1_b[c+0];
            o.y = (row[j*4+1] - mu) * rs * ln1_w[c+1] + ln1_b[c+1];
            o.z = (row[j*4+2] - mu) * rs * ln1_w[c+2] + ln1_b[c+2];
            o.w = (row[j*4+3] - mu) * rs * ln1_w[c+3] + ln1_b[c+3];
            hv[j] = o;
        }
    }
    __syncthreads();

    const int col4 = (tid & 15) * 4;   // matmul tile: 4 cols
    const int row4 = (tid >> 4) * 4;   // 4 rows

    // ---------------- q, k, v projections (weights from smem, conflict-light) ----------------
    {
        unsigned long long aq[4][2], ak[4][2], av[4][2];
        #pragma unroll
        for (int i = 0; i < 4; i++)
            #pragma unroll
            for (int j = 0; j < 2; j++) { aq[i][j] = 0ull; ak[i][j] = 0ull; av[i][j] = 0ull; }
        for (int cb = 0; cb < 64; cb += 4) {
            float a4[4][4];
            #pragma unroll
            for (int i = 0; i < 4; i++)
                *(float4*)a4[i] = *(const float4*)&sh[(row4 + i) * SHP + cb];
            #pragma unroll
            for (int kk = 0; kk < 4; kk++) {
                const int wrow = (cb + kk) * 68 + col4;   // lanes contiguous 256B
                ulonglong2 bq = *(const ulonglong2*)&wqs[wrow];
                ulonglong2 bk = *(const ulonglong2*)&wks[wrow];
                ulonglong2 bv = *(const ulonglong2*)&wvs[wrow];
                #pragma unroll
                for (int i = 0; i < 4; i++) {
                    unsigned long long aa = bcast2(a4[i][kk]);
                    fma2(aq[i][0], aa, bq.x); fma2(aq[i][1], aa, bq.y);
                    fma2(ak[i][0], aa, bk.x); fma2(ak[i][1], aa, bk.y);
                    fma2(av[i][0], aa, bv.x); fma2(av[i][1], aa, bv.y);
                }
            }
        }
        __syncthreads();   // all weight reads done before overwriting scratch
        const int cbase = (col4 >> 3) * 512 + (col4 & 7);   // h*512 + d0
        #pragma unroll
        for (int i = 0; i < 4; i++) {
            float2 q0 = unpack2(aq[i][0]), q1 = unpack2(aq[i][1]);
            float2 k0 = unpack2(ak[i][0]), k1 = unpack2(ak[i][1]);
            float2 v0 = unpack2(av[i][0]), v1 = unpack2(av[i][1]);
            const int o = cbase + (row4 + i) * 8;            // 16B-aligned (d0 in {0,4})
            *(float4*)&qc[o] = make_float4(q0.x, q0.y, q1.x, q1.y);
            *(float4*)&kc[o] = make_float4(k0.x, k0.y, k1.x, k1.y);
            *(float4*)&vc[o] = make_float4(v0.x, v0.y, v1.x, v1.y);
        }
    }
    __syncthreads();

    // ---------------- attention: streaming softmax, packed f32x2, zero shfl ----------------
    {
        const int wid  = tid >> 5;
        const int lane = tid & 31;
        const int hb   = wid * 8;
        const ulonglong2* qh2 = (const ulonglong2*)&qc[wid * 512];
        const ulonglong2* kh2 = (const ulonglong2*)&kc[wid * 512];
        const ulonglong2* vh2 = (const ulonglong2*)&vc[wid * 512];
        const int t1 = lane, t2 = lane + 32;

        unsigned long long q1p[4], q2p[4];
        {
            const unsigned long long sc = bcast2(0.125f);
            ulonglong2 a = qh2[t1 * 2], bqq = qh2[t1 * 2 + 1];
            q1p[0] = mul2(a.x, sc); q1p[1] = mul2(a.y, sc);
            q1p[2] = mul2(bqq.x, sc); q1p[3] = mul2(bqq.y, sc);
            ulonglong2 c = qh2[t2 * 2], dqq = qh2[t2 * 2 + 1];
            q2p[0] = mul2(c.x, sc); q2p[1] = mul2(c.y, sc);
            q2p[2] = mul2(dqq.x, sc); q2p[3] = mul2(dqq.y, sc);
        }
        unsigned long long acc1[4], accB[4];
        #pragma unroll
        for (int j = 0; j < 4; j++) { acc1[j] = 0ull; accB[j] = 0ull; }
        float S1 = 0.f, S2 = 0.f;

        #pragma unroll 4
        for (int s = 0; s < 32; s++) {
            ulonglong2 ka = kh2[s * 2], kb = kh2[s * 2 + 1];
            ulonglong2 va = vh2[s * 2], vb = vh2[s * 2 + 1];
            unsigned long long d1p = mul2(q1p[0], ka.x);
            fma2(d1p, q1p[1], ka.y); fma2(d1p, q1p[2], kb.x); fma2(d1p, q1p[3], kb.y);
            unsigned long long d2p = mul2(q2p[0], ka.x);
            fma2(d2p, q2p[1], ka.y); fma2(d2p, q2p[2], kb.x); fma2(d2p, q2p[3], kb.y);
            float e1 = (s <= t1) ? __expf(hadd2(d1p)) : 0.f;
            float e2 = __expf(hadd2(d2p));
            S1 += e1; S2 += e2;
            unsigned long long e1p = bcast2(e1), e2p = bcast2(e2);
            fma2(acc1[0], e1p, va.x); fma2(acc1[1], e1p, va.y);
            fma2(acc1[2], e1p, vb.x); fma2(acc1[3], e1p, vb.y);
            fma2(accB[0], e2p, va.x); fma2(accB[1], e2p, va.y);
            fma2(accB[2], e2p, vb.x); fma2(accB[3], e2p, vb.y);
        }
        #pragma unroll 4
        for (int s = 32; s < 64; s++) {
            ulonglong2 ka = kh2[s * 2], kb = kh2[s * 2 + 1];
            ulonglong2 va = vh2[s * 2], vb = vh2[s * 2 + 1];
            unsigned long long d2p = mul2(q2p[0], ka.x);
            fma2(d2p, q2p[1], ka.y); fma2(d2p, q2p[2], kb.x); fma2(d2p, q2p[3], kb.y);
            float e2 = (s <= t2) ? __expf(hadd2(d2p)) : 0.f;
            S2 += e2;
            unsigned long long e2p = bcast2(e2);
            fma2(accB[0], e2p, va.x); fma2(accB[1], e2p, va.y);
            fma2(accB[2], e2p, vb.x); fma2(accB[3], e2p, vb.y);
        }
        const float i1 = 1.0f / S1, i2 = 1.0f / S2;
        {
            float2 a0 = unpack2(acc1[0]), a1 = unpack2(acc1[1]);
            float2 a2 = unpack2(acc1[2]), a3 = unpack2(acc1[3]);
            float4* o1 = (float4*)&sh[t1 * SHP + hb];
            o1[0] = make_float4(a0.x * i1, a0.y * i1, a1.x * i1, a1.y * i1);
            o1[1] = make_float4(a2.x * i1, a2.y * i1, a3.x * i1, a3.y * i1);
            float2 b0 = unpack2(accB[0]), b1 = unpack2(accB[1]);
            float2 b2 = unpack2(accB[2]), b3 = unpack2(accB[3]);
            float4* o2 = (float4*)&sh[t2 * SHP + hb];
            o2[0] = make_float4(b0.x * i2, b0.y * i2, b1.x * i2, b1.y * i2);
            o2[1] = make_float4(b2.x * i2, b2.y * i2, b3.x * i2, b3.y * i2);
        }
    }
    __syncthreads();

    // ---------------- proj + residual into sx (packed, k-vectorized) ----------------
    {
        unsigned long long ap[4][2];
        float4 pb = *(const float4*)(proj_b + col4);
        #pragma unroll
        for (int i = 0; i < 4; i++) {
            ap[i][0] = pack2(pb.x, pb.y);
            ap[i][1] = pack2(pb.z, pb.w);
        }
        const ulonglong2* wp = (const ulonglong2*)(proj_w + col4);
        for (int cb = 0; cb < 64; cb += 4) {
            float a4[4][4];
            #pragma unroll
            for (int i = 0; i < 4; i++)
                *(float4*)a4[i] = *(const float4*)&sh[(row4 + i) * SHP + cb];
            #pragma unroll
            for (int kk = 0; kk < 4; kk++) {
                ulonglong2 bw = wp[(cb + kk) * 16];
                #pragma unroll
                for (int i = 0; i < 4; i++) {
                    unsigned long long aa = bcast2(a4[i][kk]);
                    fma2(ap[i][0], aa, bw.x);
                    fma2(ap[i][1], aa, bw.y);
                }
            }
        }
        #pragma unroll
        for (int i = 0; i < 4; i++) {
            float2 p0 = unpack2(ap[i][0]), p1 = unpack2(ap[i][1]);
            float* d = &sx[(row4 + i) * XPAD + col4];
            d[0] += p0.x; d[1] += p0.y; d[2] += p1.x; d[3] += p1.y;
        }
    }
    __syncthreads();

    // ---------------- LN2 -> sh (vectorized writes) ----------------
    {
        const float* row = &sx[lr * XPAD + lq * 16];
        float s1 = 0.f, s2 = 0.f;
        #pragma unroll
        for (int i = 0; i < 16; i++) { float v = row[i]; s1 += v; s2 += v * v; }
        s1 += __shfl_xor_sync(0xffffffffu, s1, 1);
        s2 += __shfl_xor_sync(0xffffffffu, s2, 1);
        s1 += __shfl_xor_sync(0xffffffffu, s1, 2);
        s2 += __shfl_xor_sync(0xffffffffu, s2, 2);
        float mu = s1 * 0.015625f;
        float rs = rsqrtf(s2 * 0.015625f - mu * mu + 1e-5f);
        float4* hv = (float4*)&sh[lr * SHP + lq * 16];
        #pragma unroll
        for (int j = 0; j < 4; j++) {
            int c = lq * 16 + j * 4;
            float4 o;
            o.x = (row[j*4+0] - mu) * rs * ln2_w[c+0] + ln2_b[c+0];
            o.y = (row[j*4+1] - mu) * rs * ln2_w[c+1] + ln2_b[c+1];
            o.z = (row[j*4+2] - mu) * rs * ln2_w[c+2] + ln2_b[c+2];
            o.w = (row[j*4+3] - mu) * rs * ln2_w[c+3] + ln2_b[c+3];
            hv[j] = o;
        }
    }
    __syncthreads();

    // ---------------- feed-forward in 4 chunks of 64 cols (packed, k-vectorized) ----------------
    unsigned long long acc2[4][2];
    {
        float4 b2 = *(const float4*)(fc2_b + col4);
        #pragma unroll
        for (int i = 0; i < 4; i++) {
            acc2[i][0] = pack2(b2.x, b2.y);
            acc2[i][1] = pack2(b2.z, b2.w);
        }
    }
    float* sff = qc;   // reuse scratch as [64][64]
    for (int ch = 0; ch < 4; ch++) {
        unsigned long long af[4][2];
        float4 b1 = *(const float4*)(fc1_b + ch * 64 + col4);
        #pragma unroll
        for (int i = 0; i < 4; i++) {
            af[i][0] = pack2(b1.x, b1.y);
            af[i][1] = pack2(b1.z, b1.w);
        }
        const ulonglong2* w1 = (const ulonglong2*)(fc1_w + ch * 64 + col4);
        for (int cb = 0; cb < 64; cb += 4) {
            float a4[4][4];
            #pragma unroll
            for (int i = 0; i < 4; i++)
                *(float4*)a4[i] = *(const float4*)&sh[(row4 + i) * SHP + cb];
            #pragma unroll
            for (int kk = 0; kk < 4; kk++) {
                ulonglong2 bw = w1[(cb + kk) * 64];   // +c*256 floats
                #pragma unroll
                for (int i = 0; i < 4; i++) {
                    unsigned long long aa = bcast2(a4[i][kk]);
                    fma2(af[i][0], aa, bw.x);
                    fma2(af[i][1], aa, bw.y);
                }
            }
        }
        __syncthreads();   // previous chunk's sff fully consumed
        #pragma unroll
        for (int i = 0; i < 4; i++) {
            float2 f0 = unpack2(af[i][0]), f1 = unpack2(af[i][1]);
            *(float4*)&sff[(row4 + i) * 64 + col4] =
                make_float4(fmaxf(f0.x, 0.f), fmaxf(f0.y, 0.f),
                            fmaxf(f1.x, 0.f), fmaxf(f1.y, 0.f));
        }
        __syncthreads();
        const ulonglong2* w2 = (const ulonglong2*)(fc2_w + ch * 4096 + col4);
        for (int cb = 0; cb < 64; cb += 4) {
            float a4[4][4];
            #pragma unroll
            for (int i = 0; i < 4; i++)
                *(float4*)a4[i] = *(const float4*)&sff[(row4 + i) * 64 + cb];
            #pragma unroll
            for (int kk = 0; kk < 4; kk++) {
                ulonglong2 bw = w2[(cb + kk) * 16];   // +c*64 floats
                #pragma unroll
                for (int i = 0; i < 4; i++) {
                    unsigned long long aa = bcast2(a4[i][kk]);
                    fma2(acc2[i][0], aa, bw.x);
                    fma2(acc2[i][1], aa, bw.y);
                }
            }
        }
    }

    // ---------------- final residual + store ----------------
    {
        float* ob = out + (size_t)b * 4096;
        #pragma unroll
        for (int i = 0; i < 4; i++) {
            float2 a0 = unpack2(acc2[i][0]), a1 = unpack2(acc2[i][1]);
            const float* sxr = &sx[(row4 + i) * XPAD + col4];
            float4 o;
            o.x = sxr[0] + a0.x;
            o.y = sxr[1] + a0.y;
            o.z = sxr[2] + a1.x;
            o.w = sxr[3] + a1.y;
            *(float4*)(ob + (row4 + i) * 64 + col4) = o;
        }
    }
}

extern "C" void kernel_launch(void* const* d_in, const int* in_sizes, int n_in,
                              void* d_out, int out_size)
{
    cudaFuncSetAttribute(block_kernel, cudaFuncAttributeMaxDynamicSharedMemorySize, SMEM_BYTES);
    int B = in_sizes[0] / 4096;   // B*T*C / (64*64)
    block_kernel<<<B, 256, SMEM_BYTES>>>(
        (const float*)d_in[0],
        (const float*)d_in[1],  (const float*)d_in[2],
        (const float*)d_in[3],  (const float*)d_in[4],  (const float*)d_in[5],
        (const float*)d_in[6],  (const float*)d_in[7],
        (const float*)d_in[8],  (const float*)d_in[9],
        (const float*)d_in[10], (const float*)d_in[11],
        (const float*)d_in[12], (const float*)d_in[13],
        (float*)d_out);
}